// round 1
// baseline (speedup 1.0000x reference)
#include <cuda_runtime.h>
#include <math.h>

// Problem constants
#define B_   128
#define CIN  3
#define COUT 16
#define HW   (256 * 256)          // 65536 elements per plane
#define PLANE_F4 (HW / 4)         // 16384 float4 per plane
#define NPLANES (B_ * CIN)        // 384
#define BLOCKS_PER_PLANE 4
#define THREADS 256
#define F4_PER_THREAD (PLANE_F4 / BLOCKS_PER_PLANE / THREADS)  // 16

// Scratch: per-(b,ci) plane sums. __device__ global (no allocation allowed).
__device__ float g_S[NPLANES];

__global__ void k_zero() {
    int i = blockIdx.x * blockDim.x + threadIdx.x;
    if (i < NPLANES) g_S[i] = 0.0f;
}

// Sum-reduce each (b,ci) plane of x. 4 blocks per plane, 256 thr, 16 float4/thr.
__global__ __launch_bounds__(THREADS) void k_reduce(const float4* __restrict__ x) {
    const int plane = blockIdx.x / BLOCKS_PER_PLANE;
    const int chunk = blockIdx.x % BLOCKS_PER_PLANE;
    const float4* base = x + (size_t)plane * PLANE_F4
                           + (size_t)chunk * (PLANE_F4 / BLOCKS_PER_PLANE);

    float s = 0.0f;
    #pragma unroll
    for (int i = 0; i < F4_PER_THREAD; i++) {
        float4 v = base[threadIdx.x + i * THREADS];
        s += (v.x + v.y) + (v.z + v.w);
    }

    // warp reduce
    #pragma unroll
    for (int o = 16; o > 0; o >>= 1)
        s += __shfl_xor_sync(0xFFFFFFFFu, s, o);

    __shared__ float ws[THREADS / 32];
    if ((threadIdx.x & 31) == 0) ws[threadIdx.x >> 5] = s;
    __syncthreads();

    if (threadIdx.x < THREADS / 32) {
        float t = ws[threadIdx.x];
        #pragma unroll
        for (int o = (THREADS / 64); o > 0; o >>= 1)
            t += __shfl_xor_sync(0xFFu, t, o);
        if (threadIdx.x == 0) atomicAdd(&g_S[plane], t);
    }
}

// Epilogue: mean + bias + logsumexp + *10. One block, one thread per batch.
__global__ void k_final(const float* __restrict__ weight,
                        const float* __restrict__ bias,
                        float* __restrict__ out) {
    __shared__ float wsum[CIN][COUT];
    const int t = threadIdx.x;

    if (t < CIN * COUT) {
        int ci = t / COUT, co = t % COUT;
        float s = 0.0f;
        #pragma unroll
        for (int pq = 0; pq < 9; pq++)
            s += weight[(ci * COUT + co) * 9 + pq];
        wsum[ci][co] = s;
    }
    __syncthreads();

    // t = batch index
    const float s0 = g_S[t * 3 + 0];
    const float s1 = g_S[t * 3 + 1];
    const float s2 = g_S[t * 3 + 2];
    const float inv = 1.0f / (258.0f * 258.0f);

    float y[COUT];
    float m = -INFINITY;
    #pragma unroll
    for (int co = 0; co < COUT; co++) {
        float v = (s0 * wsum[0][co] + s1 * wsum[1][co] + s2 * wsum[2][co]) * inv
                  + bias[co];
        y[co] = v;
        m = fmaxf(m, v);
    }
    float e = 0.0f;
    #pragma unroll
    for (int co = 0; co < COUT; co++)
        e += expf(y[co] - m);

    out[t] = 10.0f * (m + logf(e));
}

extern "C" void kernel_launch(void* const* d_in, const int* in_sizes, int n_in,
                              void* d_out, int out_size) {
    const float4* x      = (const float4*)d_in[0];
    const float*  weight = (const float*)d_in[1];
    const float*  bias   = (const float*)d_in[2];
    float* out = (float*)d_out;

    k_zero<<<2, 256>>>();
    k_reduce<<<NPLANES * BLOCKS_PER_PLANE, THREADS>>>(x);
    k_final<<<1, B_>>>(weight, bias, out);
}